// round 8
// baseline (speedup 1.0000x reference)
#include <cuda_runtime.h>
#include <math.h>

#define IN_DIM   512
#define HID      512
#define NSM      148
#define BPSM1    3
#define GRID1    (NSM * BPSM1)   // 444 blocks (all resident: 3/SM)
#define BLK1     512             // 4 row-workers of 128 threads each
#define NWORK    (GRID1 * 4)     // 1776 row workers (R5/R6-proven pattern)
#define NFIN     16              // blocks that run the fused finalize

// Per-block partial column sums after intra-block reduce. ~0.9 MB.
__device__ float g_scratch[GRID1 * IN_DIM];
// Grid-barrier counters (self-resetting each launch -> replay-safe).
__device__ int g_arrive = 0;
__device__ int g_depart = 0;

__device__ __forceinline__ float4 ldcg4(const float4* p) {
    float4 v;
    asm volatile("ld.global.cg.v4.f32 {%0,%1,%2,%3}, [%4];"
                 : "=f"(v.x), "=f"(v.y), "=f"(v.z), "=f"(v.w) : "l"(p));
    return v;
}

// ---------------------------------------------------------------------------
// Fused kernel: colsum (all 444 blocks) -> grid barrier -> finalize (16 blocks)
// ---------------------------------------------------------------------------
__global__ void __launch_bounds__(BLK1, BPSM1) fused_kernel(
    const float* __restrict__ X, int n_rows,
    const float* __restrict__ W_ih,
    const float* __restrict__ b_ih,
    const float* __restrict__ b_hh,
    float* __restrict__ out,
    float inv_n)
{
    const int t  = threadIdx.x;
    const int c4 = t & 127;          // float4 column 0..127
    const int g  = t >> 7;           // row-worker group 0..3
    const float4* __restrict__ Xv = (const float4*)X;
    const int S = NWORK;

    // ---- Phase 1: column sums (identical to proven R6 kernel) ----
    float4 acc0 = make_float4(0.f, 0.f, 0.f, 0.f);
    float4 acc1 = make_float4(0.f, 0.f, 0.f, 0.f);
    float4 acc2 = make_float4(0.f, 0.f, 0.f, 0.f);
    float4 acc3 = make_float4(0.f, 0.f, 0.f, 0.f);

    int r = blockIdx.x * 4 + g;
    for (; r + 7 * S < n_rows; r += 8 * S) {
        float4 v0 = Xv[(size_t)(r        ) * 128 + c4];
        float4 v1 = Xv[(size_t)(r + 1 * S) * 128 + c4];
        float4 v2 = Xv[(size_t)(r + 2 * S) * 128 + c4];
        float4 v3 = Xv[(size_t)(r + 3 * S) * 128 + c4];
        float4 v4 = Xv[(size_t)(r + 4 * S) * 128 + c4];
        float4 v5 = Xv[(size_t)(r + 5 * S) * 128 + c4];
        float4 v6 = Xv[(size_t)(r + 6 * S) * 128 + c4];
        float4 v7 = Xv[(size_t)(r + 7 * S) * 128 + c4];
        acc0.x += v0.x; acc0.y += v0.y; acc0.z += v0.z; acc0.w += v0.w;
        acc1.x += v1.x; acc1.y += v1.y; acc1.z += v1.z; acc1.w += v1.w;
        acc2.x += v2.x; acc2.y += v2.y; acc2.z += v2.z; acc2.w += v2.w;
        acc3.x += v3.x; acc3.y += v3.y; acc3.z += v3.z; acc3.w += v3.w;
        acc0.x += v4.x; acc0.y += v4.y; acc0.z += v4.z; acc0.w += v4.w;
        acc1.x += v5.x; acc1.y += v5.y; acc1.z += v5.z; acc1.w += v5.w;
        acc2.x += v6.x; acc2.y += v6.y; acc2.z += v6.z; acc2.w += v6.w;
        acc3.x += v7.x; acc3.y += v7.y; acc3.z += v7.z; acc3.w += v7.w;
    }
    for (; r < n_rows; r += S) {
        float4 v = Xv[(size_t)r * 128 + c4];
        acc0.x += v.x; acc0.y += v.y; acc0.z += v.z; acc0.w += v.w;
    }

    float4 s;
    s.x = (acc0.x + acc1.x) + (acc2.x + acc3.x);
    s.y = (acc0.y + acc1.y) + (acc2.y + acc3.y);
    s.z = (acc0.z + acc1.z) + (acc2.z + acc3.z);
    s.w = (acc0.w + acc1.w) + (acc2.w + acc3.w);

    __shared__ float4 red[3][128];
    if (g > 0) red[g - 1][c4] = s;
    __syncthreads();
    if (g == 0) {
        float4 a = red[0][c4], b = red[1][c4], c = red[2][c4];
        s.x += (a.x + b.x) + c.x;
        s.y += (a.y + b.y) + c.y;
        s.z += (a.z + b.z) + c.z;
        s.w += (a.w + b.w) + c.w;
        ((float4*)g_scratch)[(size_t)blockIdx.x * 128 + c4] = s;
    }
    __syncthreads();

    // ---- Grid barrier (release) ----
    if (t == 0) {
        __threadfence();                  // publish scratch row
        atomicAdd(&g_arrive, 1);
    }
    if (blockIdx.x >= NFIN) return;       // non-finalize blocks are done

    // ---- Finalize blocks: wait for all 444 arrivals (acquire) ----
    if (t == 0) {
        while (atomicAdd(&g_arrive, 0) < GRID1)
            __nanosleep(64);
        __threadfence();
    }
    __syncthreads();

    // ---- Phase A: reduce 444 scratch rows -> agg (L2-hot, read via .cg) ----
    __shared__ float4 part[4][128];
    __shared__ float  agg[IN_DIM];
    {
        const float4* __restrict__ sv = (const float4*)g_scratch;
        float4 ps = make_float4(0.f, 0.f, 0.f, 0.f);
        #pragma unroll 8
        for (int p = g; p < GRID1; p += 4) {
            float4 v = ldcg4(&sv[p * 128 + c4]);
            ps.x += v.x; ps.y += v.y; ps.z += v.z; ps.w += v.w;
        }
        part[g][c4] = ps;
    }
    __syncthreads();
    if (t < 128) {
        float4 a = part[0][t], b = part[1][t], c = part[2][t], d = part[3][t];
        a.x = ((a.x + b.x) + (c.x + d.x)) * inv_n;
        a.y = ((a.y + b.y) + (c.y + d.y)) * inv_n;
        a.z = ((a.z + b.z) + (c.z + d.z)) * inv_n;
        a.w = ((a.w + b.w) + (c.w + d.w)) * inv_n;
        ((float4*)agg)[t] = a;
    }
    __syncthreads();

    // ---- Phase B: 16 warps x 2 outputs = 32 outputs/block, 16 blocks ----
    const int warp = t >> 5;
    const int lane = t & 31;
    const float4* __restrict__ aggv = (const float4*)agg;

    #pragma unroll
    for (int k = 0; k < 2; k++) {
        const int i = blockIdx.x * 32 + warp * 2 + k;   // 0..511

        float acc[3];
        #pragma unroll
        for (int gg = 0; gg < 3; gg++) {
            const float4* __restrict__ row =
                (const float4*)(W_ih + (size_t)(gg * HID + i) * IN_DIM);
            float a = 0.f;
            #pragma unroll
            for (int u = 0; u < 4; u++) {
                float4 w = row[lane + u * 32];
                float4 x = aggv[lane + u * 32];
                a += w.x * x.x + w.y * x.y + w.z * x.z + w.w * x.w;
            }
            #pragma unroll
            for (int off = 16; off; off >>= 1)
                a += __shfl_xor_sync(0xFFFFFFFFu, a, off);
            acc[gg] = a;
        }

        if (lane == 0) {
            float gi_r = acc[0] + b_ih[i];
            float gi_z = acc[1] + b_ih[HID + i];
            float gi_n = acc[2] + b_ih[2 * HID + i];
            float rr = 1.f / (1.f + __expf(-(gi_r + b_hh[i])));
            float zz = 1.f / (1.f + __expf(-(gi_z + b_hh[HID + i])));
            float nn = tanhf(gi_n + rr * b_hh[2 * HID + i]);
            out[i] = (1.f - zz) * nn;   // + z*h with h=0
        }
    }

    // ---- Depart: last finalize block resets counters (replay-safe) ----
    __syncthreads();
    if (t == 0) {
        int pos = atomicAdd(&g_depart, 1);
        if (pos == NFIN - 1) {
            g_arrive = 0;
            g_depart = 0;
            __threadfence();
        }
    }
}

extern "C" void kernel_launch(void* const* d_in, const int* in_sizes, int n_in,
                              void* d_out, int out_size) {
    const float* parent_states = (const float*)d_in[0];
    const float* weight_ih     = (const float*)d_in[1];
    // d_in[2] = weight_hh : unused (h = 0 -> W_hh @ h = 0)
    const float* bias_ih       = (const float*)d_in[3];
    const float* bias_hh       = (const float*)d_in[4];
    float* out = (float*)d_out;

    const int n_rows = in_sizes[0] / IN_DIM;
    const float inv_n = 1.0f / (float)n_rows;

    fused_kernel<<<GRID1, BLK1>>>(parent_states, n_rows,
                                  weight_ih, bias_ih, bias_hh, out, inv_n);
}

// round 9
// speedup vs baseline: 1.0514x; 1.0514x over previous
#include <cuda_runtime.h>
#include <math.h>

#define IN_DIM   512
#define HID      512
#define NSM      148
#define BPSM1    3
#define GRID1    (NSM * BPSM1)   // 444 blocks
#define BLK1     512             // 4 row-workers of 128 threads each
#define NWORK    (GRID1 * 4)     // 1776 row workers (R5/R6-proven pattern)
#define NFIN     16
#define FXSCALE  4294967296.0f           // 2^32
#define FXINV    2.3283064365386963e-10  // 2^-32

// Deterministic fixed-point accumulator (int atomics are exact+commutative).
__device__ unsigned long long g_acc[IN_DIM];   // zero-init at load
__device__ int g_depart = 0;

// ---------------------------------------------------------------------------
// Kernel 1: column sums of X (n_rows x 512) -> fixed-point atomic accumulate.
// Load pattern identical to the proven R6 colsum. Tail: smem-reduce 4 row
// workers, then 128 threads issue 4 int64 atomics each (512/block).
// ---------------------------------------------------------------------------
__global__ void __launch_bounds__(BLK1, BPSM1) colsum_kernel(const float* __restrict__ X, int n_rows) {
    const int t  = threadIdx.x;
    const int c4 = t & 127;          // float4 column 0..127
    const int g  = t >> 7;           // row-worker group 0..3
    const float4* __restrict__ Xv = (const float4*)X;
    const int S = NWORK;

    float4 acc0 = make_float4(0.f, 0.f, 0.f, 0.f);
    float4 acc1 = make_float4(0.f, 0.f, 0.f, 0.f);
    float4 acc2 = make_float4(0.f, 0.f, 0.f, 0.f);
    float4 acc3 = make_float4(0.f, 0.f, 0.f, 0.f);

    int r = blockIdx.x * 4 + g;
    for (; r + 7 * S < n_rows; r += 8 * S) {
        float4 v0 = Xv[(size_t)(r        ) * 128 + c4];
        float4 v1 = Xv[(size_t)(r + 1 * S) * 128 + c4];
        float4 v2 = Xv[(size_t)(r + 2 * S) * 128 + c4];
        float4 v3 = Xv[(size_t)(r + 3 * S) * 128 + c4];
        float4 v4 = Xv[(size_t)(r + 4 * S) * 128 + c4];
        float4 v5 = Xv[(size_t)(r + 5 * S) * 128 + c4];
        float4 v6 = Xv[(size_t)(r + 6 * S) * 128 + c4];
        float4 v7 = Xv[(size_t)(r + 7 * S) * 128 + c4];
        acc0.x += v0.x; acc0.y += v0.y; acc0.z += v0.z; acc0.w += v0.w;
        acc1.x += v1.x; acc1.y += v1.y; acc1.z += v1.z; acc1.w += v1.w;
        acc2.x += v2.x; acc2.y += v2.y; acc2.z += v2.z; acc2.w += v2.w;
        acc3.x += v3.x; acc3.y += v3.y; acc3.z += v3.z; acc3.w += v3.w;
        acc0.x += v4.x; acc0.y += v4.y; acc0.z += v4.z; acc0.w += v4.w;
        acc1.x += v5.x; acc1.y += v5.y; acc1.z += v5.z; acc1.w += v5.w;
        acc2.x += v6.x; acc2.y += v6.y; acc2.z += v6.z; acc2.w += v6.w;
        acc3.x += v7.x; acc3.y += v7.y; acc3.z += v7.z; acc3.w += v7.w;
    }
    for (; r < n_rows; r += S) {
        float4 v = Xv[(size_t)r * 128 + c4];
        acc0.x += v.x; acc0.y += v.y; acc0.z += v.z; acc0.w += v.w;
    }

    float4 s;
    s.x = (acc0.x + acc1.x) + (acc2.x + acc3.x);
    s.y = (acc0.y + acc1.y) + (acc2.y + acc3.y);
    s.z = (acc0.z + acc1.z) + (acc2.z + acc3.z);
    s.w = (acc0.w + acc1.w) + (acc2.w + acc3.w);

    __shared__ float4 red[3][128];
    if (g > 0) red[g - 1][c4] = s;
    __syncthreads();
    if (g == 0) {
        float4 a = red[0][c4], b = red[1][c4], c = red[2][c4];
        s.x += (a.x + b.x) + c.x;
        s.y += (a.y + b.y) + c.y;
        s.z += (a.z + b.z) + c.z;
        s.w += (a.w + b.w) + c.w;
        // Fixed-point deterministic accumulate (exact int addition).
        long long q0 = llrintf(s.x * FXSCALE);
        long long q1 = llrintf(s.y * FXSCALE);
        long long q2 = llrintf(s.z * FXSCALE);
        long long q3 = llrintf(s.w * FXSCALE);
        atomicAdd(&g_acc[c4 * 4 + 0], (unsigned long long)q0);
        atomicAdd(&g_acc[c4 * 4 + 1], (unsigned long long)q1);
        atomicAdd(&g_acc[c4 * 4 + 2], (unsigned long long)q2);
        atomicAdd(&g_acc[c4 * 4 + 3], (unsigned long long)q3);
    }
}

// ---------------------------------------------------------------------------
// Kernel 2: finalize. grid=16, block=1024. Phase A is now one 4KB read.
// 32 warps x 1 output each (3 gate dot products of 512). gh = b_hh (h = 0).
// Accumulator self-resets (last block zeroes it) -> replay-safe.
// ---------------------------------------------------------------------------
__global__ void __launch_bounds__(1024, 1) finalize_kernel(
    const float* __restrict__ W_ih,
    const float* __restrict__ b_ih,
    const float* __restrict__ b_hh,
    float* __restrict__ out,
    float inv_n)
{
    __shared__ float agg[IN_DIM];
    __shared__ int is_last;
    const int t = threadIdx.x;

    // Phase A: load accumulator, convert fixed-point -> mean.
    if (t < IN_DIM) {
        long long v = (long long)g_acc[t];
        agg[t] = (float)((double)v * FXINV) * inv_n;
    }
    __syncthreads();

    // Depart protocol: after this block has read g_acc, count departure.
    // The last of the 16 blocks resets g_acc + counter for the next replay.
    if (t == 0) {
        __threadfence();
        int pos = atomicAdd(&g_depart, 1);
        is_last = (pos == NFIN - 1);
    }
    __syncthreads();
    if (is_last) {
        if (t < IN_DIM) g_acc[t] = 0ULL;
        if (t == 0) { g_depart = 0; __threadfence(); }
    }

    // Phase B: one warp per output i. 16 blocks * 32 warps = 512 outputs.
    const int warp = t >> 5;
    const int lane = t & 31;
    const int i = blockIdx.x * 32 + warp;
    const float4* __restrict__ aggv = (const float4*)agg;

    float acc[3];
    #pragma unroll
    for (int g = 0; g < 3; g++) {
        const float4* __restrict__ row =
            (const float4*)(W_ih + (size_t)(g * HID + i) * IN_DIM);
        float a = 0.f;
        #pragma unroll
        for (int u = 0; u < 4; u++) {
            float4 w = row[lane + u * 32];
            float4 x = aggv[lane + u * 32];
            a += w.x * x.x + w.y * x.y + w.z * x.z + w.w * x.w;
        }
        #pragma unroll
        for (int off = 16; off; off >>= 1)
            a += __shfl_xor_sync(0xFFFFFFFFu, a, off);
        acc[g] = a;
    }

    if (lane == 0) {
        float gi_r = acc[0] + b_ih[i];
        float gi_z = acc[1] + b_ih[HID + i];
        float gi_n = acc[2] + b_ih[2 * HID + i];
        float r = 1.f / (1.f + __expf(-(gi_r + b_hh[i])));
        float z = 1.f / (1.f + __expf(-(gi_z + b_hh[HID + i])));
        float n = tanhf(gi_n + r * b_hh[2 * HID + i]);
        out[i] = (1.f - z) * n;   // + z*h with h=0
    }
}

extern "C" void kernel_launch(void* const* d_in, const int* in_sizes, int n_in,
                              void* d_out, int out_size) {
    const float* parent_states = (const float*)d_in[0];
    const float* weight_ih     = (const float*)d_in[1];
    // d_in[2] = weight_hh : unused (h = 0 -> W_hh @ h = 0)
    const float* bias_ih       = (const float*)d_in[3];
    const float* bias_hh       = (const float*)d_in[4];
    float* out = (float*)d_out;

    const int n_rows = in_sizes[0] / IN_DIM;
    const float inv_n = 1.0f / (float)n_rows;

    colsum_kernel<<<GRID1, BLK1>>>(parent_states, n_rows);
    finalize_kernel<<<NFIN, 1024>>>(weight_ih, bias_ih, bias_hh, out, inv_n);
}

// round 10
// speedup vs baseline: 1.2048x; 1.1460x over previous
#include <cuda_runtime.h>
#include <math.h>

#define IN_DIM   512
#define HID      512
#define NSM      148
#define BPSM1    3
#define GRID1    (NSM * BPSM1)   // 444 blocks
#define BLK1     512             // 4 row-workers of 128 threads each
#define NWORK    (GRID1 * 4)     // 1776 row workers (R5/R6-proven pattern)
#define NFIN     16
#define NSLOT    16              // contention-spreading slots for atomics
#define FXSCALE  4294967296.0f           // 2^32
#define FXINV    2.3283064365386963e-10  // 2^-32

// Deterministic fixed-point accumulators, 16 slots to spread per-address
// atomic serialization (L2 atomics: ~27 cyc/op per address under contention).
__device__ unsigned long long g_part[NSLOT][IN_DIM];   // zero-init at load
__device__ int g_depart = 0;

// ---------------------------------------------------------------------------
// Kernel 1: column sums of X (n_rows x 512) -> fixed-point atomic accumulate
// into slot (blockIdx.x & 15). Load pattern identical to the proven R6 body.
// ---------------------------------------------------------------------------
__global__ void __launch_bounds__(BLK1, BPSM1) colsum_kernel(const float* __restrict__ X, int n_rows) {
    const int t  = threadIdx.x;
    const int c4 = t & 127;          // float4 column 0..127
    const int g  = t >> 7;           // row-worker group 0..3
    const float4* __restrict__ Xv = (const float4*)X;
    const int S = NWORK;

    float4 acc0 = make_float4(0.f, 0.f, 0.f, 0.f);
    float4 acc1 = make_float4(0.f, 0.f, 0.f, 0.f);
    float4 acc2 = make_float4(0.f, 0.f, 0.f, 0.f);
    float4 acc3 = make_float4(0.f, 0.f, 0.f, 0.f);

    int r = blockIdx.x * 4 + g;
    for (; r + 7 * S < n_rows; r += 8 * S) {
        float4 v0 = Xv[(size_t)(r        ) * 128 + c4];
        float4 v1 = Xv[(size_t)(r + 1 * S) * 128 + c4];
        float4 v2 = Xv[(size_t)(r + 2 * S) * 128 + c4];
        float4 v3 = Xv[(size_t)(r + 3 * S) * 128 + c4];
        float4 v4 = Xv[(size_t)(r + 4 * S) * 128 + c4];
        float4 v5 = Xv[(size_t)(r + 5 * S) * 128 + c4];
        float4 v6 = Xv[(size_t)(r + 6 * S) * 128 + c4];
        float4 v7 = Xv[(size_t)(r + 7 * S) * 128 + c4];
        acc0.x += v0.x; acc0.y += v0.y; acc0.z += v0.z; acc0.w += v0.w;
        acc1.x += v1.x; acc1.y += v1.y; acc1.z += v1.z; acc1.w += v1.w;
        acc2.x += v2.x; acc2.y += v2.y; acc2.z += v2.z; acc2.w += v2.w;
        acc3.x += v3.x; acc3.y += v3.y; acc3.z += v3.z; acc3.w += v3.w;
        acc0.x += v4.x; acc0.y += v4.y; acc0.z += v4.z; acc0.w += v4.w;
        acc1.x += v5.x; acc1.y += v5.y; acc1.z += v5.z; acc1.w += v5.w;
        acc2.x += v6.x; acc2.y += v6.y; acc2.z += v6.z; acc2.w += v6.w;
        acc3.x += v7.x; acc3.y += v7.y; acc3.z += v7.z; acc3.w += v7.w;
    }
    for (; r < n_rows; r += S) {
        float4 v = Xv[(size_t)r * 128 + c4];
        acc0.x += v.x; acc0.y += v.y; acc0.z += v.z; acc0.w += v.w;
    }

    float4 s;
    s.x = (acc0.x + acc1.x) + (acc2.x + acc3.x);
    s.y = (acc0.y + acc1.y) + (acc2.y + acc3.y);
    s.z = (acc0.z + acc1.z) + (acc2.z + acc3.z);
    s.w = (acc0.w + acc1.w) + (acc2.w + acc3.w);

    __shared__ float4 red[3][128];
    if (g > 0) red[g - 1][c4] = s;
    __syncthreads();
    if (g == 0) {
        float4 a = red[0][c4], b = red[1][c4], c = red[2][c4];
        s.x += (a.x + b.x) + c.x;
        s.y += (a.y + b.y) + c.y;
        s.z += (a.z + b.z) + c.z;
        s.w += (a.w + b.w) + c.w;
        // Fixed-point deterministic accumulate, spread over 16 slots.
        unsigned long long* slot = g_part[blockIdx.x & (NSLOT - 1)];
        atomicAdd(&slot[c4 * 4 + 0], (unsigned long long)llrintf(s.x * FXSCALE));
        atomicAdd(&slot[c4 * 4 + 1], (unsigned long long)llrintf(s.y * FXSCALE));
        atomicAdd(&slot[c4 * 4 + 2], (unsigned long long)llrintf(s.z * FXSCALE));
        atomicAdd(&slot[c4 * 4 + 3], (unsigned long long)llrintf(s.w * FXSCALE));
    }
}

// ---------------------------------------------------------------------------
// Kernel 2: finalize. grid=16, block=1024. Phase A: sum 16 slots (64 KB,
// exact int adds in fixed order -> deterministic), convert to mean.
// Phase B: 32 warps x 1 output each. gh = b_hh (h = 0, W_hh never read).
// Accumulators self-reset (last block zeroes them) -> replay-safe.
// ---------------------------------------------------------------------------
__global__ void __launch_bounds__(1024, 1) finalize_kernel(
    const float* __restrict__ W_ih,
    const float* __restrict__ b_ih,
    const float* __restrict__ b_hh,
    float* __restrict__ out,
    float inv_n)
{
    __shared__ float agg[IN_DIM];
    __shared__ int is_last;
    const int t = threadIdx.x;

    // Phase A: exact integer reduction across slots, fixed order.
    if (t < IN_DIM) {
        long long v = 0;
        #pragma unroll
        for (int sl = 0; sl < NSLOT; sl++)
            v += (long long)g_part[sl][t];
        agg[t] = (float)((double)v * FXINV) * inv_n;
    }
    __syncthreads();

    // Depart protocol: last of the 16 blocks resets accumulators + counter.
    if (t == 0) {
        __threadfence();
        int pos = atomicAdd(&g_depart, 1);
        is_last = (pos == NFIN - 1);
    }
    __syncthreads();
    if (is_last) {
        if (t < IN_DIM) {
            #pragma unroll
            for (int sl = 0; sl < NSLOT; sl++)
                g_part[sl][t] = 0ULL;
        }
        if (t == 0) { g_depart = 0; __threadfence(); }
    }

    // Phase B: one warp per output i. 16 blocks * 32 warps = 512 outputs.
    const int warp = t >> 5;
    const int lane = t & 31;
    const int i = blockIdx.x * 32 + warp;
    const float4* __restrict__ aggv = (const float4*)agg;

    float acc[3];
    #pragma unroll
    for (int g = 0; g < 3; g++) {
        const float4* __restrict__ row =
            (const float4*)(W_ih + (size_t)(g * HID + i) * IN_DIM);
        float a = 0.f;
        #pragma unroll
        for (int u = 0; u < 4; u++) {
            float4 w = row[lane + u * 32];
            float4 x = aggv[lane + u * 32];
            a += w.x * x.x + w.y * x.y + w.z * x.z + w.w * x.w;
        }
        #pragma unroll
        for (int off = 16; off; off >>= 1)
            a += __shfl_xor_sync(0xFFFFFFFFu, a, off);
        acc[g] = a;
    }

    if (lane == 0) {
        float gi_r = acc[0] + b_ih[i];
        float gi_z = acc[1] + b_ih[HID + i];
        float gi_n = acc[2] + b_ih[2 * HID + i];
        float r = 1.f / (1.f + __expf(-(gi_r + b_hh[i])));
        float z = 1.f / (1.f + __expf(-(gi_z + b_hh[HID + i])));
        float n = tanhf(gi_n + r * b_hh[2 * HID + i]);
        out[i] = (1.f - z) * n;   // + z*h with h=0
    }
}

extern "C" void kernel_launch(void* const* d_in, const int* in_sizes, int n_in,
                              void* d_out, int out_size) {
    const float* parent_states = (const float*)d_in[0];
    const float* weight_ih     = (const float*)d_in[1];
    // d_in[2] = weight_hh : unused (h = 0 -> W_hh @ h = 0)
    const float* bias_ih       = (const float*)d_in[3];
    const float* bias_hh       = (const float*)d_in[4];
    float* out = (float*)d_out;

    const int n_rows = in_sizes[0] / IN_DIM;
    const float inv_n = 1.0f / (float)n_rows;

    colsum_kernel<<<GRID1, BLK1>>>(parent_states, n_rows);
    finalize_kernel<<<NFIN, 1024>>>(weight_ih, bias_ih, bias_hh, out, inv_n);
}